// round 3
// baseline (speedup 1.0000x reference)
#include <cuda_runtime.h>
#include <math.h>
#include <stdint.h>

#define NB 32
#define NC 256
#define NH 64
#define NW 64
#define NHW 4096
#define NCHW (NC*NHW)
#define EPSV 1e-5f

// Scratch (allocation-free rule: __device__ globals)
__device__ float g_pooled[NB*NC];
__device__ int   g_idx[NB];
__device__ float g_feat[(size_t)NB*NCHW];     // tf32-rounded feature scratch
__device__ float g_wt[4][NC*NC];              // tf32-rounded weights: e0_pw,e1_pw,e2_pw,e2_k

__device__ __forceinline__ uint32_t f2tf32(float f) {
    uint32_t r;
    asm("cvt.rna.tf32.f32 %0, %1;" : "=r"(r) : "f"(f));
    return r;
}
__device__ __forceinline__ float f2tf32f(float f) {
    uint32_t r = f2tf32(f);
    return __uint_as_float(r);
}

// ---------------------------------------------------------------------------
// 1) Global average pool per (b,c)
// ---------------------------------------------------------------------------
__global__ void pool_kernel(const float* __restrict__ x) {
    int bc = blockIdx.x;
    const float4* p = reinterpret_cast<const float4*>(x + (size_t)bc * NHW);
    float s = 0.f;
    for (int i = threadIdx.x; i < NHW/4; i += 256) {
        float4 v = p[i];
        s += (v.x + v.y) + (v.z + v.w);
    }
    __shared__ float red[8];
    #pragma unroll
    for (int o = 16; o > 0; o >>= 1) s += __shfl_down_sync(0xffffffffu, s, o);
    if ((threadIdx.x & 31) == 0) red[threadIdx.x >> 5] = s;
    __syncthreads();
    if (threadIdx.x < 8) {
        float t = red[threadIdx.x];
        #pragma unroll
        for (int o = 4; o > 0; o >>= 1) t += __shfl_down_sync(0xffu, t, o);
        if (threadIdx.x == 0) g_pooled[bc] = t * (1.0f / NHW);
    }
}

// ---------------------------------------------------------------------------
// 2) Router: argmax of logits
// ---------------------------------------------------------------------------
__global__ void route_kernel(const float* __restrict__ rw, const float* __restrict__ rb) {
    int b = threadIdx.x;
    if (b >= NB) return;
    float best = -1e30f; int bi = 0;
    #pragma unroll
    for (int j = 0; j < 3; j++) {
        float s = rb[j];
        const float* w = rw + j*NC;
        const float* p = g_pooled + b*NC;
        for (int c = 0; c < NC; c++) s = fmaf(p[c], w[c], s);
        if (s > best) { best = s; bi = j; }
    }
    g_idx[b] = bi;
}

// ---------------------------------------------------------------------------
// 2b) Pre-convert weight matrices to tf32 (RNA) once
// ---------------------------------------------------------------------------
__global__ void prep_weights(const float* __restrict__ w0, const float* __restrict__ w1,
                             const float* __restrict__ w2, const float* __restrict__ k2) {
    int i = blockIdx.x * 256 + threadIdx.x;          // grid 1024 -> 262144 elems
    int m = i >> 16;                                  // matrix id 0..3
    int o = i & 0xFFFF;
    const float* src = (m == 0) ? w0 : (m == 1) ? w1 : (m == 2) ? w2 : k2;
    g_wt[m][o] = f2tf32f(src[o]);
}

// ---------------------------------------------------------------------------
// 3a) Depthwise 3x3 conv (dil 1 or 2) + BN + exact GELU for experts 0/1
//     Output stored tf32-rounded (consumed by tensor GEMM).
// ---------------------------------------------------------------------------
__global__ void dwconv_bn_gelu_kernel(
    const float* __restrict__ x,
    const float* __restrict__ k0, const float* __restrict__ g0, const float* __restrict__ b0,
    const float* __restrict__ m0, const float* __restrict__ v0,
    const float* __restrict__ k1, const float* __restrict__ g1, const float* __restrict__ b1,
    const float* __restrict__ m1, const float* __restrict__ v1)
{
    int b = blockIdx.z;
    int e = g_idx[b];
    if (e == 2) return;
    int c  = blockIdx.y;
    int y  = blockIdx.x * 4 + threadIdx.y;
    int xx = threadIdx.x;
    const float* kw = (e == 0 ? k0 : k1) + c * 9;
    int dil = e + 1;
    const float* xp = x + ((size_t)b*NC + c) * NHW;

    float acc = 0.f;
    #pragma unroll
    for (int dy = -1; dy <= 1; dy++) {
        int yy = y + dy*dil;
        if (yy < 0 || yy >= NH) continue;
        #pragma unroll
        for (int dx = -1; dx <= 1; dx++) {
            int xc = xx + dx*dil;
            if (xc < 0 || xc >= NW) continue;
            acc = fmaf(kw[(dy+1)*3 + (dx+1)], xp[yy*NW + xc], acc);
        }
    }
    float gg = (e == 0 ? g0[c] : g1[c]);
    float vv = (e == 0 ? v0[c] : v1[c]);
    float mm = (e == 0 ? m0[c] : m1[c]);
    float bb = (e == 0 ? b0[c] : b1[c]);
    float scale = gg * rsqrtf(vv + EPSV);
    float z = (acc - mm) * scale + bb;
    float r = z * normcdff(z);
    g_feat[((size_t)b*NC + c) * NHW + y*NW + xx] = f2tf32f(r);
}

// ---------------------------------------------------------------------------
// cp.async helpers
// ---------------------------------------------------------------------------
__device__ __forceinline__ void cp_async16(void* dst, const void* src) {
    uint32_t d = (uint32_t)__cvta_generic_to_shared(dst);
    asm volatile("cp.async.ca.shared.global [%0], [%1], 16;" :: "r"(d), "l"(src));
}
__device__ __forceinline__ void cp_commit() { asm volatile("cp.async.commit_group;"); }
__device__ __forceinline__ void cp_wait0()  { asm volatile("cp.async.wait_group 0;"); }

__device__ __forceinline__ void mma_tf32(float c[4], const uint32_t a[4], const uint32_t b[2]) {
    asm volatile(
        "mma.sync.aligned.m16n8k8.row.col.f32.tf32.tf32.f32 "
        "{%0,%1,%2,%3}, {%4,%5,%6,%7}, {%8,%9}, {%0,%1,%2,%3};"
        : "+f"(c[0]), "+f"(c[1]), "+f"(c[2]), "+f"(c[3])
        : "r"(a[0]), "r"(a[1]), "r"(a[2]), "r"(a[3]),
          "r"(b[0]), "r"(b[1]));
}

#define SPA 20    // A smem row stride (words): 20*gID mod 32 spans all banks; 80B is 16B-aligned
#define SPB 136   // B smem row stride (words): 136 mod 32 == 8 -> conflict-free frag loads

// ---------------------------------------------------------------------------
// TF32 tensor-core GEMM tile: C(128x128) = A(128x256) * B(256x128), BK=16.
// A already tf32 (g_wt). B either tf32 (cp.async path) or fp32 (CVT path).
// ---------------------------------------------------------------------------
template<bool BN_GELU, bool CVTB>
__device__ __forceinline__ void mma_gemm_tile(
    const float* __restrict__ A, const float* __restrict__ Bm, float* __restrict__ Cm,
    const float* __restrict__ p0, const float* __restrict__ p1,
    const float* __restrict__ p2, const float* __restrict__ p3)
{
    __shared__ uint32_t As[2][128][SPA];
    __shared__ uint32_t Bs[2][16][SPB];

    const int tid  = threadIdx.x;
    const int lane = tid & 31;
    const int wid  = tid >> 5;
    const int wm   = wid & 3;
    const int wn   = wid >> 2;
    const int gID  = lane >> 2;
    const int qid  = lane & 3;
    const int m0   = blockIdx.y * 128;
    const int n0   = blockIdx.x * 128;

    // A staging map: 128 rows x 16k -> 2 chunks of 16B per thread
    const int arow = tid >> 1;
    const int aq8  = (tid & 1) * 8;
    // B staging map: 16 rows(k) x 128n -> 2 chunks of 16B per thread
    const int brow = tid >> 4;
    const int bc8  = (tid & 15) * 8;

    const float* aSrcBase = A + (size_t)(m0 + arow) * NC + aq8;
    const float* bSrcBase = Bm + (size_t)brow * NHW + n0 + bc8;

    float acc[2][8][4];
    #pragma unroll
    for (int i = 0; i < 2; i++)
        #pragma unroll
        for (int j = 0; j < 8; j++)
            #pragma unroll
            for (int t = 0; t < 4; t++) acc[i][j][t] = 0.f;

    // ---- prologue: stage k0=0 into buffer 0 ----
    cp_async16(&As[0][arow][aq8],     aSrcBase);
    cp_async16(&As[0][arow][aq8 + 4], aSrcBase + 4);
    if (!CVTB) {
        cp_async16(&Bs[0][brow][bc8],     bSrcBase);
        cp_async16(&Bs[0][brow][bc8 + 4], bSrcBase + 4);
    }
    cp_commit();
    if (CVTB) {
        float4 v0 = *reinterpret_cast<const float4*>(bSrcBase);
        float4 v1 = *reinterpret_cast<const float4*>(bSrcBase + 4);
        uint4 r0 = make_uint4(f2tf32(v0.x), f2tf32(v0.y), f2tf32(v0.z), f2tf32(v0.w));
        uint4 r1 = make_uint4(f2tf32(v1.x), f2tf32(v1.y), f2tf32(v1.z), f2tf32(v1.w));
        *reinterpret_cast<uint4*>(&Bs[0][brow][bc8])     = r0;
        *reinterpret_cast<uint4*>(&Bs[0][brow][bc8 + 4]) = r1;
    }
    cp_wait0();
    __syncthreads();

    int buf = 0;
    for (int k0 = 0; k0 < NC; k0 += 16) {
        const bool has_next = (k0 + 16) < NC;
        float4 bv0, bv1;
        if (has_next) {
            const int kn = k0 + 16;
            cp_async16(&As[buf^1][arow][aq8],     aSrcBase + kn);
            cp_async16(&As[buf^1][arow][aq8 + 4], aSrcBase + kn + 4);
            if (!CVTB) {
                cp_async16(&Bs[buf^1][brow][bc8],     bSrcBase + (size_t)kn * NHW);
                cp_async16(&Bs[buf^1][brow][bc8 + 4], bSrcBase + (size_t)kn * NHW + 4);
            }
            cp_commit();
            if (CVTB) {
                bv0 = *reinterpret_cast<const float4*>(bSrcBase + (size_t)kn * NHW);
                bv1 = *reinterpret_cast<const float4*>(bSrcBase + (size_t)kn * NHW + 4);
            }
        }

        // ---- compute on smem[buf] ----
        #pragma unroll
        for (int ks = 0; ks < 2; ks++) {
            const int kb = ks * 8;
            uint32_t af[2][4], bf[8][2];
            #pragma unroll
            for (int mt = 0; mt < 2; mt++) {
                const int mb = wm*32 + mt*16;
                af[mt][0] = As[buf][mb + gID]    [kb + qid];
                af[mt][1] = As[buf][mb + gID + 8][kb + qid];
                af[mt][2] = As[buf][mb + gID]    [kb + qid + 4];
                af[mt][3] = As[buf][mb + gID + 8][kb + qid + 4];
            }
            #pragma unroll
            for (int nt = 0; nt < 8; nt++) {
                const int nb = wn*64 + nt*8;
                bf[nt][0] = Bs[buf][kb + qid]    [nb + gID];
                bf[nt][1] = Bs[buf][kb + 4 + qid][nb + gID];
            }
            #pragma unroll
            for (int mt = 0; mt < 2; mt++)
                #pragma unroll
                for (int nt = 0; nt < 8; nt++)
                    mma_tf32(acc[mt][nt], af[mt], bf[nt]);
        }

        if (has_next) {
            if (CVTB) {
                uint4 r0 = make_uint4(f2tf32(bv0.x), f2tf32(bv0.y), f2tf32(bv0.z), f2tf32(bv0.w));
                uint4 r1 = make_uint4(f2tf32(bv1.x), f2tf32(bv1.y), f2tf32(bv1.z), f2tf32(bv1.w));
                *reinterpret_cast<uint4*>(&Bs[buf^1][brow][bc8])     = r0;
                *reinterpret_cast<uint4*>(&Bs[buf^1][brow][bc8 + 4]) = r1;
            }
            cp_wait0();
            __syncthreads();
            buf ^= 1;
        }
    }

    // ---- epilogue ----
    #pragma unroll
    for (int mt = 0; mt < 2; mt++) {
        #pragma unroll
        for (int half = 0; half < 2; half++) {
            const int o = m0 + wm*32 + mt*16 + half*8 + gID;
            float sc = 0.f, mm = 0.f, bb;
            if (BN_GELU) {
                sc = p0[o] * rsqrtf(p3[o] + EPSV);
                mm = p2[o];
                bb = p1[o];
            } else {
                bb = p0[o];
            }
            float* cp = Cm + (size_t)o * NHW + n0 + wn*64 + qid*2;
            #pragma unroll
            for (int nt = 0; nt < 8; nt++) {
                float z0 = acc[mt][nt][half*2 + 0];
                float z1 = acc[mt][nt][half*2 + 1];
                if (BN_GELU) {
                    z0 = (z0 - mm) * sc + bb; z0 = z0 * normcdff(z0);
                    z1 = (z1 - mm) * sc + bb; z1 = z1 * normcdff(z1);
                    z0 = f2tf32f(z0);          // feat output feeds next GEMM: store tf32
                    z1 = f2tf32f(z1);
                } else {
                    z0 += bb; z1 += bb;        // final output: full fp32
                }
                *reinterpret_cast<float2*>(cp + nt*8) = make_float2(z0, z1);
            }
        }
    }
}

// 3b) Expert-2 feature stage: feat = bn_gelu(e2_k @ x[b]) — only for idx==2
__global__ void __launch_bounds__(256) feat_gemm_kernel(
    const float* __restrict__ x,
    const float* __restrict__ g, const float* __restrict__ bt,
    const float* __restrict__ m, const float* __restrict__ v)
{
    int b = blockIdx.z;
    if (g_idx[b] != 2) return;
    mma_gemm_tile<true, true>(g_wt[3], x + (size_t)b*NCHW, g_feat + (size_t)b*NCHW, g, bt, m, v);
}

// 4) Final pointwise: out[b] = e{idx}_pw @ feat[b] + e{idx}_pb
__global__ void __launch_bounds__(256) out_gemm_kernel(
    const float* __restrict__ pb0, const float* __restrict__ pb1,
    const float* __restrict__ pb2, float* __restrict__ out)
{
    int b = blockIdx.z;
    int e = g_idx[b];
    const float* pb = (e == 0) ? pb0 : (e == 1 ? pb1 : pb2);
    mma_gemm_tile<false, false>(g_wt[e], g_feat + (size_t)b*NCHW, out + (size_t)b*NCHW,
                                pb, nullptr, nullptr, nullptr);
}

// ---------------------------------------------------------------------------
extern "C" void kernel_launch(void* const* d_in, const int* in_sizes, int n_in,
                              void* d_out, int out_size) {
    const float* x    = (const float*)d_in[0];
    const float* rw   = (const float*)d_in[1];
    const float* rb   = (const float*)d_in[2];
    const float* e0_k = (const float*)d_in[3];
    const float* e0_g = (const float*)d_in[4];
    const float* e0_b = (const float*)d_in[5];
    const float* e0_m = (const float*)d_in[6];
    const float* e0_v = (const float*)d_in[7];
    const float* e0_pw= (const float*)d_in[8];
    const float* e0_pb= (const float*)d_in[9];
    const float* e1_k = (const float*)d_in[10];
    const float* e1_g = (const float*)d_in[11];
    const float* e1_b = (const float*)d_in[12];
    const float* e1_m = (const float*)d_in[13];
    const float* e1_v = (const float*)d_in[14];
    const float* e1_pw= (const float*)d_in[15];
    const float* e1_pb= (const float*)d_in[16];
    const float* e2_k = (const float*)d_in[17];
    const float* e2_g = (const float*)d_in[18];
    const float* e2_b = (const float*)d_in[19];
    const float* e2_m = (const float*)d_in[20];
    const float* e2_v = (const float*)d_in[21];
    const float* e2_pw= (const float*)d_in[22];
    const float* e2_pb= (const float*)d_in[23];
    float* out = (float*)d_out;

    pool_kernel<<<NB*NC, 256>>>(x);
    prep_weights<<<1024, 256>>>(e0_pw, e1_pw, e2_pw, e2_k);
    route_kernel<<<1, 32>>>(rw, rb);

    dim3 cgrid(NH/4, NC, NB);
    dwconv_bn_gelu_kernel<<<cgrid, dim3(64, 4, 1)>>>(
        x, e0_k, e0_g, e0_b, e0_m, e0_v,
           e1_k, e1_g, e1_b, e1_m, e1_v);

    dim3 ggrid(NHW/128, NC/128, NB);   // (32, 2, 32)
    feat_gemm_kernel<<<ggrid, 256>>>(x, e2_g, e2_b, e2_m, e2_v);
    out_gemm_kernel<<<ggrid, 256>>>(e0_pb, e1_pb, e2_pb, out);
}